// round 16
// baseline (speedup 1.0000x reference)
#include <cuda_runtime.h>

#define ALPHA 0.2f
#define B_   8
#define G_   8
#define V_   1024
#define FOUT_ 64
#define C_   512
#define OUTW_ 60
#define OUTC_ 120

typedef unsigned long long ull;

// ---------------- scratch ----------------
__device__ __align__(16) float    g_Wh[B_*V_*C_];
__device__ __align__(16) float    g_Spart[B_*16*C_];
__device__ __align__(16) float    g_S[B_*C_];
__device__ unsigned               g_rowmask[B_*V_*32];
__device__ int                    g_zcol[B_*V_];        // zeroed at load; re-zeroed each replay after last use
__device__ __align__(16) float    g_featout[B_*G_*V_*FOUT_];

__device__ __forceinline__ float lrelu(float x) { return x >= 0.f ? x : ALPHA * x; }

__device__ __forceinline__ ull pack2(float x, float y) {
    ull r; asm("mov.b64 %0, {%1, %2};" : "=l"(r) : "f"(x), "f"(y)); return r;
}
__device__ __forceinline__ ull bcast2(float x) {
    ull r; asm("mov.b64 %0, {%1, %1};" : "=l"(r) : "f"(x)); return r;
}
__device__ __forceinline__ ull fma2(ull a, ull b, ull c) {
    ull d; asm("fma.rn.f32x2 %0, %1, %2, %3;" : "=l"(d) : "l"(a), "l"(b), "l"(c)); return d;
}
__device__ __forceinline__ float2 unpack2(ull v) {
    float2 r; asm("mov.b64 {%0, %1}, %2;" : "=f"(r.x), "=f"(r.y) : "l"(v)); return r;
}

__global__ void k_zero() {
    int t = blockIdx.x * blockDim.x + threadIdx.x;
    if (t < B_ * V_) g_zcol[t] = 0;
}

// ---------------- adj scan, chunk of batches (b = b0 + blockIdx.y) ----------
__global__ void __launch_bounds__(256) k_adj(const int* __restrict__ adj, int b0) {
    int i = blockIdx.x, b = b0 + blockIdx.y;
    __shared__ unsigned mask[32];
    int t = threadIdx.x;
    if (t < 32) mask[t] = 0u;
    __syncthreads();
    const int4* p = (const int4*)(adj + (size_t)b * G_ * V_ * V_ + (size_t)i * V_);
    int4 acc = p[t];
#pragma unroll
    for (int g = 1; g < G_; g++) {
        int4 v = p[(size_t)g * (V_ * (V_ / 4)) + t];
        acc.x |= v.x; acc.y |= v.y; acc.z |= v.z; acc.w |= v.w;
    }
    unsigned nib = (unsigned)(acc.x == 0) | ((unsigned)(acc.y == 0) << 1) |
                   ((unsigned)(acc.z == 0) << 2) | ((unsigned)(acc.w == 0) << 3);
    if (nib) {
        atomicOr(&mask[t >> 3], nib << ((t & 7) * 4));
        int jb = b * V_ + 4 * t;
        if (acc.x == 0) atomicAdd(&g_zcol[jb + 0], 1);
        if (acc.y == 0) atomicAdd(&g_zcol[jb + 1], 1);
        if (acc.z == 0) atomicAdd(&g_zcol[jb + 2], 1);
        if (acc.w == 0) atomicAdd(&g_zcol[jb + 3], 1);
    }
    __syncthreads();
    if (t < 32) g_rowmask[((size_t)b * V_ + i) * 32 + t] = mask[t];
}

// ---------------- Wh GEMM, chunk of batches (b = b0 + blockIdx.z) -----------
__global__ void __launch_bounds__(256) k_wh(const float* __restrict__ h,
                                            const float* __restrict__ W, int b0) {
    __shared__ __align__(16) float sW[64 * 64];
    __shared__ __align__(16) float sH[64 * 64];
    __shared__ float red[64 * 17];
    int t = threadIdx.x;
    int vt = blockIdx.x, g = blockIdx.y, b = b0 + blockIdx.z;
    const float4* wp = (const float4*)(W + (size_t)g * 4096);
    const float4* hp = (const float4*)(h + (((size_t)b * G_ + g) * V_ + (size_t)vt * 64) * 64);
    float4* sw4 = (float4*)sW;
    float4* sh4 = (float4*)sH;
#pragma unroll
    for (int q = t; q < 1024; q += 256) { sw4[q] = wp[q]; sh4[q] = hp[q]; }
    __syncthreads();
    int tx = t & 15, ty = t >> 4;
    int o0 = tx * 4, r0 = ty * 4;
    float acc[4][4] = {};
#pragma unroll 4
    for (int i = 0; i < 64; i++) {
        float4 bb = *(const float4*)(sW + i * 64 + o0);
#pragma unroll
        for (int r = 0; r < 4; r++) {
            float a = sH[(r0 + r) * 64 + i];
            acc[r][0] += a * bb.x; acc[r][1] += a * bb.y;
            acc[r][2] += a * bb.z; acc[r][3] += a * bb.w;
        }
    }
    float cs[4] = {0.f, 0.f, 0.f, 0.f};
#pragma unroll
    for (int r = 0; r < 4; r++) {
        float4 v;
        v.x = lrelu(acc[r][0]); v.y = lrelu(acc[r][1]);
        v.z = lrelu(acc[r][2]); v.w = lrelu(acc[r][3]);
        size_t row = (size_t)b * V_ + vt * 64 + r0 + r;
        *(float4*)(g_Wh + row * C_ + g * 64 + o0) = v;
        cs[0] += v.x; cs[1] += v.y; cs[2] += v.z; cs[3] += v.w;
    }
    __syncthreads();
#pragma unroll
    for (int j = 0; j < 4; j++) red[(o0 + j) * 17 + ty] = cs[j];
    __syncthreads();
    if (t < 64) {
        float s = 0.f;
#pragma unroll
        for (int k = 0; k < 16; k++) s += red[t * 17 + k];
        g_Spart[((size_t)b * 16 + vt) * C_ + g * 64 + t] = s;
    }
}

// ---------------- S reduce, chunk (grid = nb*8) ----------------
__global__ void k_sreduce(int b0) {
    int b = b0 + (blockIdx.x >> 3);
    int c = (blockIdx.x & 7) * 64 + threadIdx.x;
    float s = 0.f;
#pragma unroll
    for (int vt = 0; vt < 16; vt++) s += g_Spart[((size_t)b * 16 + vt) * C_ + c];
    g_S[b * C_ + c] = s;
}

// ---------------- featout, chunk ----------------
__global__ void __launch_bounds__(128) k_featout(int b0) {
    int i = blockIdx.x, b = b0 + blockIdx.y;
    int t = threadIdx.x;
    __shared__ short jlist[64];
    __shared__ int njs;

    if (t < 32) {
        unsigned mw = g_rowmask[((size_t)b * V_ + i) * 32 + t];
        int cnt = __popc(mw);
        int pre = cnt;
#pragma unroll
        for (int d = 1; d < 32; d <<= 1) {
            int v = __shfl_up_sync(0xffffffffu, pre, d);
            if (t >= d) pre += v;
        }
        int excl = pre - cnt;
        if (t == 31) njs = pre;
        while (mw) {
            int p = __ffs(mw) - 1;
            mw &= mw - 1;
            jlist[excl++] = (short)(t * 32 + p);
        }
    }
    __syncthreads();

    const float4* whb = (const float4*)(g_Wh + (size_t)b * V_ * C_) + t;
    float4 S = ((const float4*)(g_S + b * C_))[t];
    float cx = 0.f, cy = 0.f, cz = 0.f, cw = 0.f;
    int n = njs;
#pragma unroll 1
    for (int k = 0; k < n; k += 2) {
        float4 v0 = whb[(size_t)jlist[k] * 128];
        float4 v1 = (k + 1 < n) ? whb[(size_t)jlist[k + 1] * 128]
                                : make_float4(0.f, 0.f, 0.f, 0.f);
        cx += v0.x + v1.x; cy += v0.y + v1.y;
        cz += v0.z + v1.z; cw += v0.w + v1.w;
    }
    float4 fout;
    fout.x = lrelu((S.x - cx) * (1.0f / V_)); fout.y = lrelu((S.y - cy) * (1.0f / V_));
    fout.z = lrelu((S.z - cz) * (1.0f / V_)); fout.w = lrelu((S.w - cw) * (1.0f / V_));

    int g = t >> 4, o4 = t & 15;
    *(float4*)(g_featout + (((size_t)b * G_ + g) * V_ + i) * FOUT_ + o4 * 4) = fout;
}

// ---------------- conv, chunk; which=0 fuses featin ----------
__global__ void __launch_bounds__(512) k_conv(const float* __restrict__ cw,
                                              const float* __restrict__ cb,
                                              float* __restrict__ out,
                                              int which, int b0) {
    int b = b0 + blockIdx.y;
    int r0 = blockIdx.x * 16;
    int coloff = which ? OUTW_ : 0;

    __shared__ __align__(16) float sin_[8][20][64];
    __shared__ __align__(8) float2 swt2[4 * 8 * 25];
    __shared__ float2 sb2[4];
    __shared__ float sdeg[20];

    int t = threadIdx.x;
    if (which == 0 && t < 20) {
        int v = r0 - 2 + t;
        sdeg[t] = (v >= 0 && v < V_)
                ? (float)(V_ - g_zcol[b * V_ + v]) * (1.0f / V_) : 0.f;
    }
    for (int q = t; q < 800; q += 512) {
        int gg = q / 200;
        int rem = q - gg * 200;
        swt2[q] = make_float2(cw[(2 * gg) * 200 + rem], cw[(2 * gg + 1) * 200 + rem]);
    }
    if (t < 4) sb2[t] = make_float2(cb[2 * t], cb[2 * t + 1]);
    __syncthreads();

    if (which) {
#pragma unroll
        for (int q = t; q < 2560; q += 512) {
            int cin = q / 320;
            int rem = q - cin * 320;
            int row = rem >> 4;
            int o4  = rem & 15;
            int v = r0 - 2 + row;
            float4 val = make_float4(0.f, 0.f, 0.f, 0.f);
            if (v >= 0 && v < V_)
                val = *(const float4*)(g_featout + (((size_t)b * G_ + cin) * V_ + v) * FOUT_ + o4 * 4);
            *(float4*)(&sin_[cin][row][o4 * 4]) = val;
        }
    } else {
#pragma unroll
        for (int q = t; q < 2560; q += 512) {
            int cin = q / 320;
            int rem = q - cin * 320;
            int row = rem >> 4;
            int o4  = rem & 15;
            int v = r0 - 2 + row;
            float4 val = make_float4(0.f, 0.f, 0.f, 0.f);
            if (v >= 0 && v < V_) {
                float4 wv = *(const float4*)(g_Wh + ((size_t)b * V_ + v) * C_ + cin * 64 + o4 * 4);
                float d = sdeg[row];
                val.x = lrelu(d * wv.x); val.y = lrelu(d * wv.y);
                val.z = lrelu(d * wv.z); val.w = lrelu(d * wv.w);
            }
            *(float4*)(&sin_[cin][row][o4 * 4]) = val;
        }
    }
    __syncthreads();

    int cg = t & 15, rg = (t >> 4) & 7, gg = t >> 7;
    if (cg < 15) {
        int w0 = cg * 4;
        int lr = rg * 2;

        ull bias = pack2(sb2[gg].x, sb2[gg].y);
        ull acc[2][4];
#pragma unroll
        for (int r = 0; r < 2; r++)
#pragma unroll
            for (int c = 0; c < 4; c++) acc[r][c] = bias;

        const float2* wp = &swt2[gg * 200];

#pragma unroll 1
        for (int cin = 0; cin < 8; cin++) {
#pragma unroll
            for (int kh = 0; kh < 5; kh++) {
                ull in2[2][8];
#pragma unroll
                for (int rr = 0; rr < 2; rr++) {
                    float4 a4 = *(const float4*)(&sin_[cin][lr + kh + rr][w0]);
                    float4 b4 = *(const float4*)(&sin_[cin][lr + kh + rr][w0 + 4]);
                    in2[rr][0] = bcast2(a4.x); in2[rr][1] = bcast2(a4.y);
                    in2[rr][2] = bcast2(a4.z); in2[rr][3] = bcast2(a4.w);
                    in2[rr][4] = bcast2(b4.x); in2[rr][5] = bcast2(b4.y);
                    in2[rr][6] = bcast2(b4.z); in2[rr][7] = bcast2(b4.w);
                }
#pragma unroll
                for (int kw = 0; kw < 5; kw++) {
                    float2 w2 = wp[cin * 25 + kh * 5 + kw];
                    ull wt = pack2(w2.x, w2.y);
#pragma unroll
                    for (int r = 0; r < 2; r++) {
#pragma unroll
                        for (int c = 0; c < 4; c++)
                            acc[r][c] = fma2(in2[r][kw + c], wt, acc[r][c]);
                    }
                }
            }
        }

#pragma unroll
        for (int r = 0; r < 2; r++) {
            float2 u0 = unpack2(acc[r][0]);
            float2 u1 = unpack2(acc[r][1]);
            float2 u2 = unpack2(acc[r][2]);
            float2 u3 = unpack2(acc[r][3]);
            int v = r0 + lr + r;
            size_t base0 = (((size_t)b * G_ + (2 * gg)) * V_ + v) * OUTC_ + coloff + w0;
            size_t base1 = (((size_t)b * G_ + (2 * gg + 1)) * V_ + v) * OUTC_ + coloff + w0;
            *(float4*)(out + base0) = make_float4(u0.x, u1.x, u2.x, u3.x);
            *(float4*)(out + base1) = make_float4(u0.y, u1.y, u2.y, u3.y);
        }
    }
}

// ---------------- launch: 3-chunk [2,3,3] batch pipeline ----------
extern "C" void kernel_launch(void* const* d_in, const int* in_sizes, int n_in,
                              void* d_out, int out_size) {
    const float* h       = (const float*)d_in[0];
    const int*   adj     = (const int*)d_in[1];
    const float* W       = (const float*)d_in[2];
    const float* conv1_w = (const float*)d_in[3];
    const float* conv1_b = (const float*)d_in[4];
    const float* conv2_w = (const float*)d_in[5];
    const float* conv2_b = (const float*)d_in[6];
    float* out = (float*)d_out;

    static cudaStream_t s1 = nullptr, s2 = nullptr, s3 = nullptr;
    static cudaEvent_t ev0, evA0, evA1, evA2, evW0, evW1, evS0, evS1, evJ1, evJ2, evJ3;
    if (s1 == nullptr) {
        cudaStreamCreateWithFlags(&s1, cudaStreamNonBlocking);
        cudaStreamCreateWithFlags(&s2, cudaStreamNonBlocking);
        cudaStreamCreateWithFlags(&s3, cudaStreamNonBlocking);
        cudaEventCreateWithFlags(&ev0, cudaEventDisableTiming);
        cudaEventCreateWithFlags(&evA0, cudaEventDisableTiming);
        cudaEventCreateWithFlags(&evA1, cudaEventDisableTiming);
        cudaEventCreateWithFlags(&evA2, cudaEventDisableTiming);
        cudaEventCreateWithFlags(&evW0, cudaEventDisableTiming);
        cudaEventCreateWithFlags(&evW1, cudaEventDisableTiming);
        cudaEventCreateWithFlags(&evS0, cudaEventDisableTiming);
        cudaEventCreateWithFlags(&evS1, cudaEventDisableTiming);
        cudaEventCreateWithFlags(&evJ1, cudaEventDisableTiming);
        cudaEventCreateWithFlags(&evJ2, cudaEventDisableTiming);
        cudaEventCreateWithFlags(&evJ3, cudaEventDisableTiming);
    }

    // fork workers
    cudaEventRecord(ev0, 0);
    cudaStreamWaitEvent(s1, ev0, 0);
    cudaStreamWaitEvent(s2, ev0, 0);
    cudaStreamWaitEvent(s3, ev0, 0);

    // s1: wh + sreduce in [2,6] chunks (fma-bound; overlaps adj stream)
    k_wh<<<dim3(16, G_, 2), 256, 0, s1>>>(h, W, 0);
    cudaEventRecord(evW0, s1);
    k_sreduce<<<16, 64, 0, s1>>>(0);
    cudaEventRecord(evS0, s1);
    k_wh<<<dim3(16, G_, 6), 256, 0, s1>>>(h, W, 2);
    cudaEventRecord(evW1, s1);
    k_sreduce<<<48, 64, 0, s1>>>(2);
    cudaEventRecord(evS1, s1);

    // legacy: adj in [2,3,3] chunks
    k_adj<<<dim3(V_, 2), 256>>>(adj, 0);
    cudaEventRecord(evA0, 0);
    k_adj<<<dim3(V_, 3), 256>>>(adj, 2);
    cudaEventRecord(evA1, 0);
    k_adj<<<dim3(V_, 3), 256>>>(adj, 5);
    cudaEventRecord(evA2, 0);

    // s2: conv1 (featin fused) per chunk -> re-zero zcol
    cudaStreamWaitEvent(s2, evW0, 0);
    cudaStreamWaitEvent(s2, evA0, 0);
    k_conv<<<dim3(V_ / 16, 2), 512, 0, s2>>>(conv1_w, conv1_b, out, 0, 0);
    cudaStreamWaitEvent(s2, evW1, 0);
    cudaStreamWaitEvent(s2, evA1, 0);
    k_conv<<<dim3(V_ / 16, 3), 512, 0, s2>>>(conv1_w, conv1_b, out, 0, 2);
    cudaStreamWaitEvent(s2, evA2, 0);
    k_conv<<<dim3(V_ / 16, 3), 512, 0, s2>>>(conv1_w, conv1_b, out, 0, 5);
    k_zero<<<8, 1024, 0, s2>>>();

    // s3: featout + conv2 per chunk (evS implies the matching Wh chunk)
    cudaStreamWaitEvent(s3, evS0, 0);
    cudaStreamWaitEvent(s3, evA0, 0);
    k_featout<<<dim3(V_, 2), 128, 0, s3>>>(0);
    k_conv<<<dim3(V_ / 16, 2), 512, 0, s3>>>(conv2_w, conv2_b, out, 1, 0);
    cudaStreamWaitEvent(s3, evS1, 0);
    cudaStreamWaitEvent(s3, evA1, 0);
    k_featout<<<dim3(V_, 3), 128, 0, s3>>>(2);
    k_conv<<<dim3(V_ / 16, 3), 512, 0, s3>>>(conv2_w, conv2_b, out, 1, 2);
    cudaStreamWaitEvent(s3, evA2, 0);
    k_featout<<<dim3(V_, 3), 128, 0, s3>>>(5);
    k_conv<<<dim3(V_ / 16, 3), 512, 0, s3>>>(conv2_w, conv2_b, out, 1, 5);

    // join
    cudaEventRecord(evJ1, s1);
    cudaEventRecord(evJ2, s2);
    cudaEventRecord(evJ3, s3);
    cudaStreamWaitEvent(0, evJ1, 0);
    cudaStreamWaitEvent(0, evJ2, 0);
    cudaStreamWaitEvent(0, evJ3, 0);
}